// round 16
// baseline (speedup 1.0000x reference)
#include <cuda_runtime.h>
#include <cuda_bf16.h>
#include <cuda_fp16.h>
#include <stdint.h>

#define N_NODES 100000
#define N_EDGES 1600000
#define D_IN    256
#define D_OUT   128
#define N_TILES ((N_NODES + 127) / 128)   // 782

// ---------------- device scratch (no allocations allowed) ----------------
__device__ uint32_t g_support_h[(size_t)N_NODES * (D_OUT / 2)];   // 25.6 MB
__device__ int   g_counts[N_NODES];
__device__ int   g_rowptr[N_NODES + 1];
__device__ int   g_cursor[N_NODES];
__device__ int2  g_sorted_cv[N_EDGES];

#define SCAN_B 1024
#define NSB    ((N_NODES + SCAN_B - 1) / SCAN_B)       // 98
__device__ int   g_blocksums[NSB];

// ---------------- 1) fp16 HMMA GEMM: support = X @ W ---------------------
// 512 threads, 1 CTA/SM, 128x128 tile.  128-k double-stages: 8 A-buffers,
// one __syncthreads per 128 k (2 per tile).
#define WSTRIDE 132
#define ASTRIDE 20
#define W_U32   (128 * WSTRIDE)            // 16896
#define A_U32S  (128 * ASTRIDE)            // 2560 (one 32-k block)
#define SM_TOTAL_B ((W_U32 + 8 * A_U32S) * 4)   // 149504 bytes

__device__ __forceinline__ uint32_t pack_h2(float f0, float f1) {
    uint32_t r;
    asm("cvt.rn.f16x2.f32 %0, %1, %2;" : "=r"(r) : "f"(f1), "f"(f0));
    return r;
}

__device__ __forceinline__ void mma_f16(float* d, const uint32_t* a, const uint32_t* b) {
    asm volatile(
        "mma.sync.aligned.m16n8k16.row.col.f32.f16.f16.f32 "
        "{%0,%1,%2,%3}, {%4,%5,%6,%7}, {%8,%9}, {%0,%1,%2,%3};"
        : "+f"(d[0]), "+f"(d[1]), "+f"(d[2]), "+f"(d[3])
        : "r"(a[0]), "r"(a[1]), "r"(a[2]), "r"(a[3]), "r"(b[0]), "r"(b[1]));
}

__global__ __launch_bounds__(512, 1)
void gemm_mma_kernel(const float* __restrict__ A, const float* __restrict__ W) {
    extern __shared__ uint32_t smem[];
    uint32_t* w_s   = smem;                // [128][WSTRIDE]
    uint32_t* a_buf = smem + W_U32;        // [8 blocks][A_U32S]; stage s = blocks 4s..4s+3

    const int tid    = threadIdx.x;
    const int wid    = tid >> 5;           // 0..15
    const int lane   = tid & 31;
    const int warp_m = wid & 3;            // 4 row-bands of 32
    const int warp_n = wid >> 2;           // 4 col-bands of 32
    const int g      = lane >> 2;
    const int c      = lane & 3;

    // ---- W prologue: fp32 -> fp16 pairs into SMEM ----
    for (int idx = tid; idx < D_IN * D_OUT; idx += 512) {
        const int n = idx & 127;
        const int k = idx >> 7;
        __half h = __float2half_rn(W[(size_t)k * D_OUT + n]);
        ((uint16_t*)&w_s[n * WSTRIDE + (k >> 1)])[k & 1] = *(uint16_t*)&h;
    }
    __syncthreads();

    const int a_row = tid >> 2;            // 0..127
    const int a_q   = tid & 3;             // 8-float quarter within each 32-k block

    // ---- register prefetch of one 128-k half-row: 8 float4 ----
    float4 pf[8];
    {
        const int gr = blockIdx.x * 128 + a_row;
        if (blockIdx.x < N_TILES && gr < N_NODES) {
            const float* base = A + (size_t)gr * D_IN;
#pragma unroll
            for (int b = 0; b < 4; b++) {
                const float4* q = (const float4*)(base + b * 32 + a_q * 8);
                pf[2 * b]     = q[0];
                pf[2 * b + 1] = q[1];
            }
        } else {
#pragma unroll
            for (int j = 0; j < 8; j++) pf[j] = make_float4(0.f, 0.f, 0.f, 0.f);
        }
    }

    for (int tile = blockIdx.x; tile < N_TILES; tile += gridDim.x) {
        const int m0 = tile * 128;

        float acc[2][4][4];
#pragma unroll
        for (int mt = 0; mt < 2; mt++)
#pragma unroll
            for (int nt = 0; nt < 4; nt++)
#pragma unroll
                for (int q = 0; q < 4; q++) acc[mt][nt][q] = 0.f;

        for (int kbp = 0; kbp < 2; kbp++) {            // 128-k half-stages
            const int st = kbp & 1;
            uint32_t* asb = a_buf + st * 4 * A_U32S;   // 4 consecutive 32-k blocks

            // ---- convert prefetched regs + store 4 blocks (4x STS.128) ----
            {
#pragma unroll
                for (int b = 0; b < 4; b++) {
                    const float4 v0 = pf[2 * b], v1 = pf[2 * b + 1];
                    uint4 t = make_uint4(pack_h2(v0.x, v0.y), pack_h2(v0.z, v0.w),
                                         pack_h2(v1.x, v1.y), pack_h2(v1.z, v1.w));
                    *(uint4*)(asb + b * A_U32S + a_row * ASTRIDE + a_q * 4) = t;
                }
            }

            // ---- issue prefetch for next 128-k (or next tile) ----
            {
                int nk = kbp + 1, ntile = tile;
                if (nk == 2) { nk = 0; ntile = tile + gridDim.x; }
                const int gr = ntile * 128 + a_row;
                if (ntile < N_TILES && gr < N_NODES) {
                    const float* base = A + (size_t)gr * D_IN + nk * 128;
#pragma unroll
                    for (int b = 0; b < 4; b++) {
                        const float4* q = (const float4*)(base + b * 32 + a_q * 8);
                        pf[2 * b]     = q[0];
                        pf[2 * b + 1] = q[1];
                    }
                } else {
#pragma unroll
                    for (int j = 0; j < 8; j++) pf[j] = make_float4(0.f, 0.f, 0.f, 0.f);
                }
            }
            __syncthreads();

            // ---- compute: 8 k16 steps across the 4 blocks ----
#pragma unroll
            for (int q = 0; q < 8; q++) {
                uint32_t* as = asb + (q >> 1) * A_U32S;
                const int kpl = (q & 1) * 8 + c;            // local kpair in block
                const int kpg = kbp * 64 + q * 8 + c;       // global kpair for W

                uint32_t av[2][4];
#pragma unroll
                for (int mt = 0; mt < 2; mt++) {
                    const int r0 = (warp_m * 32 + mt * 16 + g) * ASTRIDE;
                    const int r1 = r0 + 8 * ASTRIDE;
                    av[mt][0] = as[r0 + kpl];
                    av[mt][1] = as[r1 + kpl];
                    av[mt][2] = as[r0 + kpl + 4];
                    av[mt][3] = as[r1 + kpl + 4];
                }
                uint32_t bv[4][2];
#pragma unroll
                for (int nt = 0; nt < 4; nt++) {
                    const int n = warp_n * 32 + nt * 8 + g;
                    bv[nt][0] = w_s[n * WSTRIDE + kpg];
                    bv[nt][1] = w_s[n * WSTRIDE + kpg + 4];
                }
#pragma unroll
                for (int mt = 0; mt < 2; mt++)
#pragma unroll
                    for (int nt = 0; nt < 4; nt++)
                        mma_f16(acc[mt][nt], av[mt], bv[nt]);
            }
        }

        // ---- epilogue: convert to fp16 (half2 per u32) ----
#pragma unroll
        for (int mt = 0; mt < 2; mt++) {
            const int r0 = m0 + warp_m * 32 + mt * 16 + g;
#pragma unroll
            for (int nt = 0; nt < 4; nt++) {
                const int u = warp_n * 16 + nt * 4 + c;
                if (r0 < N_NODES) {
                    __half2 h = __floats2half2_rn(acc[mt][nt][0], acc[mt][nt][1]);
                    g_support_h[(size_t)r0 * (D_OUT / 2) + u] = *(uint32_t*)&h;
                }
                if (r0 + 8 < N_NODES) {
                    __half2 h = __floats2half2_rn(acc[mt][nt][2], acc[mt][nt][3]);
                    g_support_h[(size_t)(r0 + 8) * (D_OUT / 2) + u] = *(uint32_t*)&h;
                }
            }
        }
        __syncthreads();
    }
}

// ---------------- 2) CSR build: histogram -> scan -> scatter -------------
__global__ void hist4_kernel(const int* __restrict__ rows) {
    int t = blockIdx.x * blockDim.x + threadIdx.x;
    if (t * 4 >= N_EDGES) return;
    int4 r = ((const int4*)rows)[t];
    atomicAdd(&g_counts[r.x], 1);
    atomicAdd(&g_counts[r.y], 1);
    atomicAdd(&g_counts[r.z], 1);
    atomicAdd(&g_counts[r.w], 1);
}

__global__ __launch_bounds__(SCAN_B)
void scan1_kernel() {
    __shared__ int sh[SCAN_B];
    int i = blockIdx.x * SCAN_B + threadIdx.x;
    int v = (i < N_NODES) ? g_counts[i] : 0;
    sh[threadIdx.x] = v;
    __syncthreads();
#pragma unroll
    for (int off = 1; off < SCAN_B; off <<= 1) {
        int t = (threadIdx.x >= off) ? sh[threadIdx.x - off] : 0;
        __syncthreads();
        sh[threadIdx.x] += t;
        __syncthreads();
    }
    if (i < N_NODES) g_rowptr[i] = sh[threadIdx.x] - v;
    if (threadIdx.x == SCAN_B - 1) g_blocksums[blockIdx.x] = sh[SCAN_B - 1];
}

__global__ __launch_bounds__(256)
void scan23_kernel() {
    __shared__ int sh[256];
    const int t = threadIdx.x;
    const int v = (t < NSB) ? g_blocksums[t] : 0;
    sh[t] = v;
    __syncthreads();
#pragma unroll
    for (int off = 1; off < 256; off <<= 1) {
        int x = (t >= off) ? sh[t - off] : 0;
        __syncthreads();
        sh[t] += x;
        __syncthreads();
    }
    __shared__ int base;
    if (t == 0) {
        const int seg = (blockIdx.x * 256) / SCAN_B;
        base = sh[seg] - g_blocksums[seg];
    }
    __syncthreads();
    const int i = blockIdx.x * 256 + t;
    if (i < N_NODES) {
        const int val = g_rowptr[i] + base;
        g_rowptr[i] = val;
        g_cursor[i] = val;
    }
    if (i == 0) g_rowptr[N_NODES] = N_EDGES;
}

__global__ void scatter4_kernel(const int* __restrict__ rows,
                                const int* __restrict__ cols,
                                const float* __restrict__ vals) {
    int t = blockIdx.x * blockDim.x + threadIdx.x;
    if (t * 4 >= N_EDGES) return;
    int4   r = ((const int4*)rows)[t];
    int4   c = ((const int4*)cols)[t];
    float4 v = ((const float4*)vals)[t];
    int p0 = atomicAdd(&g_cursor[r.x], 1);
    int p1 = atomicAdd(&g_cursor[r.y], 1);
    int p2 = atomicAdd(&g_cursor[r.z], 1);
    int p3 = atomicAdd(&g_cursor[r.w], 1);
    g_sorted_cv[p0] = make_int2(c.x, __float_as_int(v.x));
    g_sorted_cv[p1] = make_int2(c.y, __float_as_int(v.y));
    g_sorted_cv[p2] = make_int2(c.z, __float_as_int(v.z));
    g_sorted_cv[p3] = make_int2(c.w, __float_as_int(v.w));
}

// ---------------- 3) Aggregate: warp/row, shfl-broadcast edge data -------
__global__ __launch_bounds__(256)
void aggregate_kernel(const float* __restrict__ bias, float* __restrict__ out) {
    int w    = (blockIdx.x * blockDim.x + threadIdx.x) >> 5;
    int lane = threadIdx.x & 31;
    if (w >= N_NODES) return;

    const int s = g_rowptr[w];
    const int e = g_rowptr[w + 1];

    float4 acc = ((const float4*)bias)[lane];

    for (int base = s; base < e; base += 32) {
        const int rem = e - base;
        int2 cv = make_int2(0, 0);
        if (lane < rem) cv = g_sorted_cv[base + lane];
        const int n = rem < 32 ? rem : 32;

#pragma unroll 8
        for (int j = 0; j < n; j++) {
            const int   col = __shfl_sync(0xFFFFFFFFu, cv.x, j);
            const float v   = __int_as_float(__shfl_sync(0xFFFFFFFFu, cv.y, j));
            uint2 sv = *(const uint2*)&g_support_h[(size_t)col * 64 + lane * 2];
            float2 a = __half22float2(*(__half2*)&sv.x);
            float2 b = __half22float2(*(__half2*)&sv.y);
            acc.x += v * a.x; acc.y += v * a.y; acc.z += v * b.x; acc.w += v * b.y;
        }
    }

    *(float4*)&out[(size_t)w * D_OUT + lane * 4] = acc;
}

// ---------------- launch ------------------------------------------------
extern "C" void kernel_launch(void* const* d_in, const int* in_sizes, int n_in,
                              void* d_out, int out_size) {
    const float* in_feature = (const float*)d_in[0];
    const int*   edge_rows  = (const int*)d_in[1];
    const int*   edge_cols  = (const int*)d_in[2];
    const float* edge_vals  = (const float*)d_in[3];
    const float* weight     = (const float*)d_in[4];
    const float* bias       = (const float*)d_in[5];
    float*       out        = (float*)d_out;

    (void)in_sizes; (void)n_in; (void)out_size;

    static cudaStream_t s2 = 0;
    static cudaEvent_t ev_fork = 0, ev_join = 0;
    static void* counts_ptr = 0;
    static int init_done = 0;
    if (!init_done) {
        cudaFuncSetAttribute(gemm_mma_kernel, cudaFuncAttributeMaxDynamicSharedMemorySize, SM_TOTAL_B);
        cudaStreamCreateWithFlags(&s2, cudaStreamNonBlocking);
        cudaEventCreateWithFlags(&ev_fork, cudaEventDisableTiming);
        cudaEventCreateWithFlags(&ev_join, cudaEventDisableTiming);
        cudaGetSymbolAddress(&counts_ptr, g_counts);
        init_done = 1;
    }

    // fork: CSR build (s2) runs concurrently with GEMM (main stream)
    cudaEventRecord(ev_fork, 0);
    cudaStreamWaitEvent(s2, ev_fork, 0);

    // --- s2: CSR build front half ---
    cudaMemsetAsync(counts_ptr, 0, N_NODES * sizeof(int), s2);
    hist4_kernel<<<(N_EDGES / 4 + 255) / 256, 256, 0, s2>>>(edge_rows);
    scan1_kernel<<<NSB, SCAN_B, 0, s2>>>();
    scan23_kernel<<<(N_NODES + 255) / 256, 256, 0, s2>>>();

    // --- main stream: GEMM (ncu capture slot) ---
    gemm_mma_kernel<<<148, 512, SM_TOTAL_B>>>(in_feature, weight);

    // --- s2: CSR back half ---
    scatter4_kernel<<<(N_EDGES / 4 + 255) / 256, 256, 0, s2>>>(edge_rows, edge_cols, edge_vals);

    // join
    cudaEventRecord(ev_join, s2);
    cudaStreamWaitEvent(0, ev_join, 0);

    // 3) out = A @ support + bias   (one warp per row)
    int blocks = (N_NODES * 32 + 255) / 256;
    aggregate_kernel<<<blocks, 256>>>(bias, out);
}

// round 17
// speedup vs baseline: 1.0054x; 1.0054x over previous
#include <cuda_runtime.h>
#include <cuda_bf16.h>
#include <cuda_fp16.h>
#include <stdint.h>

#define N_NODES 100000
#define N_EDGES 1600000
#define D_IN    256
#define D_OUT   128
#define N_TILES ((N_NODES + 127) / 128)   // 782

// ---------------- device scratch (no allocations allowed) ----------------
__device__ uint32_t g_support_h[(size_t)N_NODES * (D_OUT / 2)];   // 25.6 MB
__device__ int   g_counts[N_NODES];
__device__ int   g_rowptr[N_NODES + 1];
__device__ int   g_cursor[N_NODES];
__device__ int2  g_sorted_cv[N_EDGES];

#define SCAN_B 1024
#define NSB    ((N_NODES + SCAN_B - 1) / SCAN_B)       // 98
__device__ int   g_blocksums[NSB];

// ---------------- 1) fp16 HMMA GEMM: support = X @ W ---------------------
// 512 threads, 1 CTA/SM, 128x128 tile.  128-k double-stages: 8 A-buffers,
// one __syncthreads per 128 k (2 per tile).
#define WSTRIDE 132
#define ASTRIDE 20
#define W_U32   (128 * WSTRIDE)            // 16896
#define A_U32S  (128 * ASTRIDE)            // 2560 (one 32-k block)
#define SM_TOTAL_B ((W_U32 + 8 * A_U32S) * 4)   // 149504 bytes

__device__ __forceinline__ uint32_t pack_h2(float f0, float f1) {
    uint32_t r;
    asm("cvt.rn.f16x2.f32 %0, %1, %2;" : "=r"(r) : "f"(f1), "f"(f0));
    return r;
}

__device__ __forceinline__ void mma_f16(float* d, const uint32_t* a, const uint32_t* b) {
    asm volatile(
        "mma.sync.aligned.m16n8k16.row.col.f32.f16.f16.f32 "
        "{%0,%1,%2,%3}, {%4,%5,%6,%7}, {%8,%9}, {%0,%1,%2,%3};"
        : "+f"(d[0]), "+f"(d[1]), "+f"(d[2]), "+f"(d[3])
        : "r"(a[0]), "r"(a[1]), "r"(a[2]), "r"(a[3]), "r"(b[0]), "r"(b[1]));
}

__global__ __launch_bounds__(512, 1)
void gemm_mma_kernel(const float* __restrict__ A, const float* __restrict__ W) {
    extern __shared__ uint32_t smem[];
    uint32_t* w_s   = smem;                // [128][WSTRIDE]
    uint32_t* a_buf = smem + W_U32;        // [8 blocks][A_U32S]; stage s = blocks 4s..4s+3

    const int tid    = threadIdx.x;
    const int wid    = tid >> 5;           // 0..15
    const int lane   = tid & 31;
    const int warp_m = wid & 3;            // 4 row-bands of 32
    const int warp_n = wid >> 2;           // 4 col-bands of 32
    const int g      = lane >> 2;
    const int c      = lane & 3;

    // ---- W prologue: fp32 -> fp16 pairs into SMEM ----
    for (int idx = tid; idx < D_IN * D_OUT; idx += 512) {
        const int n = idx & 127;
        const int k = idx >> 7;
        __half h = __float2half_rn(W[(size_t)k * D_OUT + n]);
        ((uint16_t*)&w_s[n * WSTRIDE + (k >> 1)])[k & 1] = *(uint16_t*)&h;
    }
    __syncthreads();

    const int a_row = tid >> 2;            // 0..127
    const int a_q   = tid & 3;             // 8-float quarter within each 32-k block

    // ---- register prefetch of one 128-k half-row: 8 float4 ----
    float4 pf[8];
    {
        const int gr = blockIdx.x * 128 + a_row;
        if (blockIdx.x < N_TILES && gr < N_NODES) {
            const float* base = A + (size_t)gr * D_IN;
#pragma unroll
            for (int b = 0; b < 4; b++) {
                const float4* q = (const float4*)(base + b * 32 + a_q * 8);
                pf[2 * b]     = q[0];
                pf[2 * b + 1] = q[1];
            }
        } else {
#pragma unroll
            for (int j = 0; j < 8; j++) pf[j] = make_float4(0.f, 0.f, 0.f, 0.f);
        }
    }

    for (int tile = blockIdx.x; tile < N_TILES; tile += gridDim.x) {
        const int m0 = tile * 128;

        float acc[2][4][4];
#pragma unroll
        for (int mt = 0; mt < 2; mt++)
#pragma unroll
            for (int nt = 0; nt < 4; nt++)
#pragma unroll
                for (int q = 0; q < 4; q++) acc[mt][nt][q] = 0.f;

        for (int kbp = 0; kbp < 2; kbp++) {            // 128-k half-stages
            const int st = kbp & 1;
            uint32_t* asb = a_buf + st * 4 * A_U32S;   // 4 consecutive 32-k blocks

            // ---- convert prefetched regs + store 4 blocks (4x STS.128) ----
            {
#pragma unroll
                for (int b = 0; b < 4; b++) {
                    const float4 v0 = pf[2 * b], v1 = pf[2 * b + 1];
                    uint4 t = make_uint4(pack_h2(v0.x, v0.y), pack_h2(v0.z, v0.w),
                                         pack_h2(v1.x, v1.y), pack_h2(v1.z, v1.w));
                    *(uint4*)(asb + b * A_U32S + a_row * ASTRIDE + a_q * 4) = t;
                }
            }

            // ---- issue prefetch for next 128-k (or next tile) ----
            {
                int nk = kbp + 1, ntile = tile;
                if (nk == 2) { nk = 0; ntile = tile + gridDim.x; }
                const int gr = ntile * 128 + a_row;
                if (ntile < N_TILES && gr < N_NODES) {
                    const float* base = A + (size_t)gr * D_IN + nk * 128;
#pragma unroll
                    for (int b = 0; b < 4; b++) {
                        const float4* q = (const float4*)(base + b * 32 + a_q * 8);
                        pf[2 * b]     = q[0];
                        pf[2 * b + 1] = q[1];
                    }
                } else {
#pragma unroll
                    for (int j = 0; j < 8; j++) pf[j] = make_float4(0.f, 0.f, 0.f, 0.f);
                }
            }
            __syncthreads();

            // ---- compute: 8 k16 steps across the 4 blocks ----
#pragma unroll
            for (int q = 0; q < 8; q++) {
                uint32_t* as = asb + (q >> 1) * A_U32S;
                const int kpl = (q & 1) * 8 + c;            // local kpair in block
                const int kpg = kbp * 64 + q * 8 + c;       // global kpair for W

                uint32_t av[2][4];
#pragma unroll
                for (int mt = 0; mt < 2; mt++) {
                    const int r0 = (warp_m * 32 + mt * 16 + g) * ASTRIDE;
                    const int r1 = r0 + 8 * ASTRIDE;
                    av[mt][0] = as[r0 + kpl];
                    av[mt][1] = as[r1 + kpl];
                    av[mt][2] = as[r0 + kpl + 4];
                    av[mt][3] = as[r1 + kpl + 4];
                }
                uint32_t bv[4][2];
#pragma unroll
                for (int nt = 0; nt < 4; nt++) {
                    const int n = warp_n * 32 + nt * 8 + g;
                    bv[nt][0] = w_s[n * WSTRIDE + kpg];
                    bv[nt][1] = w_s[n * WSTRIDE + kpg + 4];
                }
#pragma unroll
                for (int mt = 0; mt < 2; mt++)
#pragma unroll
                    for (int nt = 0; nt < 4; nt++)
                        mma_f16(acc[mt][nt], av[mt], bv[nt]);
            }
        }

        // ---- epilogue: convert to fp16 (half2 per u32) ----
#pragma unroll
        for (int mt = 0; mt < 2; mt++) {
            const int r0 = m0 + warp_m * 32 + mt * 16 + g;
#pragma unroll
            for (int nt = 0; nt < 4; nt++) {
                const int u = warp_n * 16 + nt * 4 + c;
                if (r0 < N_NODES) {
                    __half2 h = __floats2half2_rn(acc[mt][nt][0], acc[mt][nt][1]);
                    g_support_h[(size_t)r0 * (D_OUT / 2) + u] = *(uint32_t*)&h;
                }
                if (r0 + 8 < N_NODES) {
                    __half2 h = __floats2half2_rn(acc[mt][nt][2], acc[mt][nt][3]);
                    g_support_h[(size_t)(r0 + 8) * (D_OUT / 2) + u] = *(uint32_t*)&h;
                }
            }
        }
        __syncthreads();
    }
}

// ---------------- 2) CSR build: histogram -> scan -> scatter -------------
// hist: 8 edges per thread (2x int4 loads, 8 REDs)
__global__ void hist8_kernel(const int* __restrict__ rows) {
    int t = blockIdx.x * blockDim.x + threadIdx.x;
    if (t >= N_EDGES / 8) return;
    const int4* r4 = (const int4*)rows + t * 2;
    int4 a = r4[0], b = r4[1];
    atomicAdd(&g_counts[a.x], 1); atomicAdd(&g_counts[a.y], 1);
    atomicAdd(&g_counts[a.z], 1); atomicAdd(&g_counts[a.w], 1);
    atomicAdd(&g_counts[b.x], 1); atomicAdd(&g_counts[b.y], 1);
    atomicAdd(&g_counts[b.z], 1); atomicAdd(&g_counts[b.w], 1);
}

// warp-shfl scan: 256 threads x 4 elements = 1024 nodes per block
__global__ __launch_bounds__(256)
void scan1_kernel() {
    __shared__ int warp_sums[8];
    const int t    = threadIdx.x;
    const int lane = t & 31;
    const int wid  = t >> 5;
    const int idx  = blockIdx.x * SCAN_B + t * 4;

    int4 v = make_int4(0, 0, 0, 0);
    if (idx < N_NODES) v = *(const int4*)&g_counts[idx];   // N_NODES % 4 == 0

    const int s0 = v.x, s1 = s0 + v.y, s2 = s1 + v.z, s3 = s2 + v.w;
    int incl = s3;
#pragma unroll
    for (int off = 1; off < 32; off <<= 1) {
        int n = __shfl_up_sync(0xFFFFFFFFu, incl, off);
        if (lane >= off) incl += n;
    }
    if (lane == 31) warp_sums[wid] = incl;
    __syncthreads();
    if (wid == 0) {
        int ws = (lane < 8) ? warp_sums[lane] : 0;
#pragma unroll
        for (int off = 1; off < 8; off <<= 1) {
            int n = __shfl_up_sync(0xFFFFFFFFu, ws, off);
            if (lane >= off) ws += n;
        }
        if (lane < 8) warp_sums[lane] = ws;                // inclusive warp prefix
    }
    __syncthreads();
    const int warp_excl   = (wid == 0) ? 0 : warp_sums[wid - 1];
    const int thread_excl = warp_excl + incl - s3;
    if (idx < N_NODES) {
        g_rowptr[idx + 0] = thread_excl;
        g_rowptr[idx + 1] = thread_excl + s0;
        g_rowptr[idx + 2] = thread_excl + s1;
        g_rowptr[idx + 3] = thread_excl + s2;
    }
    if (t == 255) g_blocksums[blockIdx.x] = warp_sums[7];  // block total
}

// merged scan2+scan3 (unchanged semantics: blocksums are block totals)
__global__ __launch_bounds__(256)
void scan23_kernel() {
    __shared__ int sh[256];
    const int t = threadIdx.x;
    const int v = (t < NSB) ? g_blocksums[t] : 0;
    sh[t] = v;
    __syncthreads();
#pragma unroll
    for (int off = 1; off < 256; off <<= 1) {
        int x = (t >= off) ? sh[t - off] : 0;
        __syncthreads();
        sh[t] += x;
        __syncthreads();
    }
    __shared__ int base;
    if (t == 0) {
        const int seg = (blockIdx.x * 256) / SCAN_B;
        base = sh[seg] - g_blocksums[seg];
    }
    __syncthreads();
    const int i = blockIdx.x * 256 + t;
    if (i < N_NODES) {
        const int val = g_rowptr[i] + base;
        g_rowptr[i] = val;
        g_cursor[i] = val;
    }
    if (i == 0) g_rowptr[N_NODES] = N_EDGES;
}

__global__ void scatter4_kernel(const int* __restrict__ rows,
                                const int* __restrict__ cols,
                                const float* __restrict__ vals) {
    int t = blockIdx.x * blockDim.x + threadIdx.x;
    if (t * 4 >= N_EDGES) return;
    int4   r = ((const int4*)rows)[t];
    int4   c = ((const int4*)cols)[t];
    float4 v = ((const float4*)vals)[t];
    int p0 = atomicAdd(&g_cursor[r.x], 1);
    int p1 = atomicAdd(&g_cursor[r.y], 1);
    int p2 = atomicAdd(&g_cursor[r.z], 1);
    int p3 = atomicAdd(&g_cursor[r.w], 1);
    g_sorted_cv[p0] = make_int2(c.x, __float_as_int(v.x));
    g_sorted_cv[p1] = make_int2(c.y, __float_as_int(v.y));
    g_sorted_cv[p2] = make_int2(c.z, __float_as_int(v.z));
    g_sorted_cv[p3] = make_int2(c.w, __float_as_int(v.w));
}

// ---------------- 3) Aggregate: warp/row, shfl-broadcast edge data -------
__global__ __launch_bounds__(256)
void aggregate_kernel(const float* __restrict__ bias, float* __restrict__ out) {
    int w    = (blockIdx.x * blockDim.x + threadIdx.x) >> 5;
    int lane = threadIdx.x & 31;
    if (w >= N_NODES) return;

    const int s = g_rowptr[w];
    const int e = g_rowptr[w + 1];

    float4 acc = ((const float4*)bias)[lane];

    for (int base = s; base < e; base += 32) {
        const int rem = e - base;
        int2 cv = make_int2(0, 0);
        if (lane < rem) cv = g_sorted_cv[base + lane];
        const int n = rem < 32 ? rem : 32;

#pragma unroll 8
        for (int j = 0; j < n; j++) {
            const int   col = __shfl_sync(0xFFFFFFFFu, cv.x, j);
            const float v   = __int_as_float(__shfl_sync(0xFFFFFFFFu, cv.y, j));
            uint2 sv = *(const uint2*)&g_support_h[(size_t)col * 64 + lane * 2];
            float2 a = __half22float2(*(__half2*)&sv.x);
            float2 b = __half22float2(*(__half2*)&sv.y);
            acc.x += v * a.x; acc.y += v * a.y; acc.z += v * b.x; acc.w += v * b.y;
        }
    }

    *(float4*)&out[(size_t)w * D_OUT + lane * 4] = acc;
}

// ---------------- launch ------------------------------------------------
extern "C" void kernel_launch(void* const* d_in, const int* in_sizes, int n_in,
                              void* d_out, int out_size) {
    const float* in_feature = (const float*)d_in[0];
    const int*   edge_rows  = (const int*)d_in[1];
    const int*   edge_cols  = (const int*)d_in[2];
    const float* edge_vals  = (const float*)d_in[3];
    const float* weight     = (const float*)d_in[4];
    const float* bias       = (const float*)d_in[5];
    float*       out        = (float*)d_out;

    (void)in_sizes; (void)n_in; (void)out_size;

    static cudaStream_t s2 = 0;
    static cudaEvent_t ev_fork = 0, ev_join = 0;
    static void* counts_ptr = 0;
    static int init_done = 0;
    if (!init_done) {
        cudaFuncSetAttribute(gemm_mma_kernel, cudaFuncAttributeMaxDynamicSharedMemorySize, SM_TOTAL_B);
        cudaStreamCreateWithFlags(&s2, cudaStreamNonBlocking);
        cudaEventCreateWithFlags(&ev_fork, cudaEventDisableTiming);
        cudaEventCreateWithFlags(&ev_join, cudaEventDisableTiming);
        cudaGetSymbolAddress(&counts_ptr, g_counts);
        init_done = 1;
    }

    // fork BEFORE the GEMM so the CSR branch is independent of it
    cudaEventRecord(ev_fork, 0);
    cudaStreamWaitEvent(s2, ev_fork, 0);

    // --- main stream: GEMM FIRST (its CTAs get resident before CSR blocks) ---
    gemm_mma_kernel<<<148, 512, SM_TOTAL_B>>>(in_feature, weight);

    // --- s2: CSR build ---
    cudaMemsetAsync(counts_ptr, 0, N_NODES * sizeof(int), s2);
    hist8_kernel<<<(N_EDGES / 8 + 255) / 256, 256, 0, s2>>>(edge_rows);
    scan1_kernel<<<NSB, 256, 0, s2>>>();
    scan23_kernel<<<(N_NODES + 255) / 256, 256, 0, s2>>>();
    scatter4_kernel<<<(N_EDGES / 4 + 255) / 256, 256, 0, s2>>>(edge_rows, edge_cols, edge_vals);

    // join
    cudaEventRecord(ev_join, s2);
    cudaStreamWaitEvent(0, ev_join, 0);

    // 3) out = A @ support + bias   (one warp per row)
    int blocks = (N_NODES * 32 + 255) / 256;
    aggregate_kernel<<<blocks, 256>>>(bias, out);
}